// round 15
// baseline (speedup 1.0000x reference)
#include <cuda_runtime.h>
#include <cuda_bf16.h>
#include <cstdint>

#define NB     16
#define CC     64
#define WHT    16384
#define CWH    (CC * WHT)
#define SPLITS 32

// Scratch (device globals; allocation is forbidden)
__device__ float g_gram_part[2 * NB * SPLITS * CC * CC];
__device__ float g_sums_part[2 * NB * SPLITS * CC];
__device__ float g_logits[NB * 2 * CC * CC];
__device__ float g_att[NB * 2 * CC * CC];

__device__ __forceinline__ uint32_t smem_u32(const void* p) {
    uint32_t a;
    asm("{ .reg .u64 t; cvta.to.shared.u64 t, %1; cvt.u32.u64 %0, t; }" : "=r"(a) : "l"(p));
    return a;
}
__device__ __forceinline__ uint32_t cvt_tf32(float x) {
    uint32_t r;
    asm("cvt.rna.tf32.f32 %0, %1;" : "=r"(r) : "f"(x));
    return r;
}
__device__ __forceinline__ void ldsm4(uint32_t* r, uint32_t addr) {
    asm volatile("ldmatrix.sync.aligned.m8n8.x4.shared.b16 {%0,%1,%2,%3}, [%4];"
                 : "=r"(r[0]), "=r"(r[1]), "=r"(r[2]), "=r"(r[3]) : "r"(addr));
}
__device__ __forceinline__ void ldsm4t(uint32_t* r, uint32_t addr) {
    asm volatile("ldmatrix.sync.aligned.m8n8.x4.trans.shared.b16 {%0,%1,%2,%3}, [%4];"
                 : "=r"(r[0]), "=r"(r[1]), "=r"(r[2]), "=r"(r[3]) : "r"(addr));
}
__device__ __forceinline__ void mma8(float* d, const uint32_t* a, const uint32_t* b) {
    asm volatile(
        "mma.sync.aligned.m16n8k8.row.col.f32.tf32.tf32.f32 "
        "{%0,%1,%2,%3}, {%4,%5,%6,%7}, {%8,%9}, {%0,%1,%2,%3};"
        : "+f"(d[0]), "+f"(d[1]), "+f"(d[2]), "+f"(d[3])
        : "r"(a[0]), "r"(a[1]), "r"(a[2]), "r"(a[3]), "r"(b[0]), "r"(b[1]));
}
__device__ __forceinline__ void mma16bf(float* d, const uint32_t* a, const uint32_t* b) {
    asm volatile(
        "mma.sync.aligned.m16n8k16.row.col.f32.bf16.bf16.f32 "
        "{%0,%1,%2,%3}, {%4,%5,%6,%7}, {%8,%9}, {%0,%1,%2,%3};"
        : "+f"(d[0]), "+f"(d[1]), "+f"(d[2]), "+f"(d[3])
        : "r"(a[0]), "r"(a[1]), "r"(a[2]), "r"(a[3]), "r"(b[0]), "r"(b[1]));
}
__device__ __forceinline__ uint32_t pack_bf16x2(float e0, float e1) {
    uint32_t r;
    asm("cvt.rn.bf16x2.f32 %0, %1, %2;" : "=r"(r) : "f"(e1), "f"(e0));
    return r;
}
__device__ __forceinline__ float bf16hi_f32(float x) {
    __nv_bfloat16 b = __float2bfloat16_rn(x);
    return __bfloat162float(b);
}

// ---------------------------------------------------------------------------
// Kernel 1: gram partials via mma.sync tf32 hi/lo, double-buffered.
// QUADRANT ownership: each of 4 warps owns a 32x32 output quadrant
// (mh = w>>1, nh = w&1) and covers ALL 4 k8 chunks. acc shrinks 64 -> 32
// floats/thread -> fits 5 CTAs/SM (reg cap 102): 20 warps/SM (was 16).
// No cross-warp reduce: disjoint quadrants written directly.
// grid = 2*16*32 = 1024 blocks (mat, n, split of 512 px), 128 threads.
// ---------------------------------------------------------------------------
__global__ void __launch_bounds__(128, 5) gram_mma_kernel(const float* __restrict__ xR,
                                                          const float* __restrict__ xT) {
    __shared__ uint32_t sY[2][128 * 36];   // 2 x 18432 B ping-pong

    int bid = blockIdx.x;
    int split = bid & 31;
    int n = (bid >> 5) & 15;
    int mat = bid >> 9;
    const float* src = (mat ? xT : xR) + n * CWH;

    int tid = threadIdx.x;
    int w = tid >> 5;
    int lane = tid & 31;
    int mrow = (w >> 1) * 32;   // quadrant row base
    int ncol = (w & 1) * 32;    // quadrant col base

    int sc = tid >> 1;
    int psb = (tid & 1) * 64;
    const float* gsrc = src + sc * WHT + split * 512 + (tid & 1) * 16;

    uint32_t buf0 = smem_u32(sY[0]);
    uint32_t stoff_hi = (uint32_t)(sc * 144 + psb);
    uint32_t stoff_lo = stoff_hi + 64 * 144;

    int q  = lane >> 3;
    int r8 = lane & 7;
    int a_row  = r8 + ((q & 1) << 3);
    int a_colb = (q >> 1) << 4;
    int b_row  = r8 + ((q >> 1) << 3);
    int b_colb = (q & 1) << 4;

    float acc[2][4][4];
#pragma unroll
    for (int i = 0; i < 2; i++)
#pragma unroll
        for (int j = 0; j < 4; j++)
#pragma unroll
            for (int e = 0; e < 4; e++) acc[i][j][e] = 0.0f;
    float csum = 0.0f;

    float4 v[4];
#pragma unroll
    for (int i = 0; i < 4; i++) v[i] = *(const float4*)(gsrc + 4 * i);
    // stage t=0 into buf 0
    {
        uint32_t hi = buf0 + stoff_hi, lo = buf0 + stoff_lo;
#pragma unroll
        for (int i = 0; i < 4; i++) {
            float4 x = v[i];
            csum += (x.x + x.y) + (x.z + x.w);
            uint32_t hx = cvt_tf32(x.x), hy = cvt_tf32(x.y);
            uint32_t hz = cvt_tf32(x.z), hw = cvt_tf32(x.w);
            uint32_t lx = cvt_tf32(x.x - __uint_as_float(hx));
            uint32_t ly = cvt_tf32(x.y - __uint_as_float(hy));
            uint32_t lz = cvt_tf32(x.z - __uint_as_float(hz));
            uint32_t lw = cvt_tf32(x.w - __uint_as_float(hw));
            asm volatile("st.shared.v4.b32 [%0], {%1,%2,%3,%4};" ::
                         "r"(hi + i * 16), "r"(hx), "r"(hy), "r"(hz), "r"(hw) : "memory");
            asm volatile("st.shared.v4.b32 [%0], {%1,%2,%3,%4};" ::
                         "r"(lo + i * 16), "r"(lx), "r"(ly), "r"(lz), "r"(lw) : "memory");
        }
    }
    __syncthreads();

#pragma unroll 1
    for (int t = 0; t < 16; t++) {
        uint32_t cbuf = buf0 + (uint32_t)((t & 1) * 18432);
        uint32_t nbuf = buf0 + (uint32_t)(((t + 1) & 1) * 18432);

        // (1) issue global loads for t+1 (non-blocking)
        if (t < 15) {
            const float* nxt = gsrc + (t + 1) * 32;
#pragma unroll
            for (int i = 0; i < 4; i++) v[i] = *(const float4*)(nxt + 4 * i);
        }

        // (2) compute: ALL 4 k8 chunks on this warp's quadrant
#pragma unroll
        for (int k8 = 0; k8 < 4; k8++) {
            uint32_t kb = (uint32_t)(k8 * 32);
            uint32_t Ah[2][4], Al[2][4], Bh[2][4], Bl[2][4];
#pragma unroll
            for (int mt = 0; mt < 2; mt++) {
                uint32_t addr = cbuf + (mrow + mt * 16 + a_row) * 144 + kb + a_colb;
                ldsm4(Ah[mt], addr);
                ldsm4(Al[mt], addr + 64 * 144);
            }
#pragma unroll
            for (int nt16 = 0; nt16 < 2; nt16++) {
                uint32_t addr = cbuf + (ncol + nt16 * 16 + b_row) * 144 + kb + b_colb;
                ldsm4(Bh[nt16], addr);
                ldsm4(Bl[nt16], addr + 64 * 144);
            }
#pragma unroll
            for (int mt = 0; mt < 2; mt++)
#pragma unroll
                for (int nt = 0; nt < 4; nt++) {
                    const uint32_t* bh = &Bh[nt >> 1][(nt & 1) * 2];
                    const uint32_t* bl = &Bl[nt >> 1][(nt & 1) * 2];
                    mma8(acc[mt][nt], Ah[mt], bh);   // hi*hi
                    mma8(acc[mt][nt], Ah[mt], bl);   // hi*lo
                    mma8(acc[mt][nt], Al[mt], bh);   // lo*hi
                }
        }

        // (3) cvt + store t+1 into nbuf (stalls on LDG here, after mma issued)
        if (t < 15) {
            uint32_t hi = nbuf + stoff_hi, lo = nbuf + stoff_lo;
#pragma unroll
            for (int i = 0; i < 4; i++) {
                float4 x = v[i];
                csum += (x.x + x.y) + (x.z + x.w);
                uint32_t hx = cvt_tf32(x.x), hy = cvt_tf32(x.y);
                uint32_t hz = cvt_tf32(x.z), hw = cvt_tf32(x.w);
                uint32_t lx = cvt_tf32(x.x - __uint_as_float(hx));
                uint32_t ly = cvt_tf32(x.y - __uint_as_float(hy));
                uint32_t lz = cvt_tf32(x.z - __uint_as_float(hz));
                uint32_t lw = cvt_tf32(x.w - __uint_as_float(hw));
                asm volatile("st.shared.v4.b32 [%0], {%1,%2,%3,%4};" ::
                             "r"(hi + i * 16), "r"(hx), "r"(hy), "r"(hz), "r"(hw) : "memory");
                asm volatile("st.shared.v4.b32 [%0], {%1,%2,%3,%4};" ::
                             "r"(lo + i * 16), "r"(lx), "r"(ly), "r"(lz), "r"(lw) : "memory");
            }
        }
        __syncthreads();
    }

    // channel sums
    csum += __shfl_xor_sync(0xffffffffu, csum, 1);
    if ((tid & 1) == 0)
        g_sums_part[((mat * NB + n) * SPLITS + split) * 64 + sc] = csum;

    // direct write: each warp owns a disjoint 32x32 quadrant
    {
        float* gb = g_gram_part + ((mat * NB + n) * SPLITS + split) * 4096;
        int gr = lane >> 2, tig = lane & 3;
#pragma unroll
        for (int mt = 0; mt < 2; mt++)
#pragma unroll
            for (int nt = 0; nt < 4; nt++) {
                int row = mrow + mt * 16 + gr;
                int col = ncol + nt * 8 + 2 * tig;
                *(float2*)&gb[row * 64 + col] =
                    make_float2(acc[mt][nt][0], acc[mt][nt][1]);
                *(float2*)&gb[(row + 8) * 64 + col] =
                    make_float2(acc[mt][nt][2], acc[mt][nt][3]);
            }
    }
}

// ---------------------------------------------------------------------------
// Kernel 2: logits (unchanged)
// ---------------------------------------------------------------------------
__global__ void __launch_bounds__(256) logits_kernel(const float* __restrict__ WR,
                                                     const float* __restrict__ bR,
                                                     const float* __restrict__ WT,
                                                     const float* __restrict__ bT) {
    int n = blockIdx.x & 15;
    int mat = blockIdx.x >> 4;
    const float* W  = mat ? WT : WR;
    const float* bv = mat ? bT : bR;

    __shared__ float sW[64][64];
    __shared__ float sGM[64][65];
    __shared__ float sb[64], ssum[64], su[64];

    int tid = threadIdx.x;
    for (int i = tid; i < 1024; i += 256)
        ((float4*)&sW[0][0])[i] = ((const float4*)W)[i];

    const float4* gp = (const float4*)(g_gram_part + (mat * NB + n) * SPLITS * 4096);
    for (int i = tid; i < 1024; i += 256) {
        float4 a = gp[i];
#pragma unroll
        for (int s = 1; s < SPLITS; s++) {
            float4 b = gp[s * 1024 + i];
            a.x += b.x; a.y += b.y; a.z += b.z; a.w += b.w;
        }
        int row = i >> 4, col = (i & 15) * 4;
        sGM[row][col] = a.x; sGM[row][col + 1] = a.y;
        sGM[row][col + 2] = a.z; sGM[row][col + 3] = a.w;
    }
    if (tid < 64) {
        sb[tid] = bv[tid];
        const float* sp = g_sums_part + (mat * NB + n) * SPLITS * 64 + tid;
        float s = 0.0f;
#pragma unroll
        for (int k = 0; k < SPLITS; k++) s += sp[k * 64];
        ssum[tid] = s;
    }
    __syncthreads();

    if (tid < 64) {
        float u = 0.0f;
        for (int f = 0; f < 64; f++) u += sW[tid][f] * ssum[f];
        su[tid] = u;
    }

    int r = tid >> 4, q = tid & 15;
    float acc[4][4];
#pragma unroll
    for (int i = 0; i < 4; i++)
#pragma unroll
        for (int j = 0; j < 4; j++) acc[i][j] = 0.0f;
    for (int f = 0; f < 64; f++) {
        float wv[4], gv[4];
#pragma unroll
        for (int i = 0; i < 4; i++) wv[i] = sW[4 * r + i][f];
#pragma unroll
        for (int j = 0; j < 4; j++) gv[j] = sGM[f][4 * q + j];
#pragma unroll
        for (int i = 0; i < 4; i++)
#pragma unroll
            for (int j = 0; j < 4; j++) acc[i][j] = fmaf(wv[i], gv[j], acc[i][j]);
    }
    __syncthreads();
#pragma unroll
    for (int i = 0; i < 4; i++)
#pragma unroll
        for (int j = 0; j < 4; j++) sGM[4 * r + i][4 * q + j] = acc[i][j];
    __syncthreads();

#pragma unroll
    for (int i = 0; i < 4; i++)
#pragma unroll
        for (int j = 0; j < 4; j++) acc[i][j] = 0.0f;
    for (int e = 0; e < 64; e++) {
        float mv[4], wv[4];
#pragma unroll
        for (int i = 0; i < 4; i++) mv[i] = sGM[4 * r + i][e];
#pragma unroll
        for (int j = 0; j < 4; j++) wv[j] = sW[4 * q + j][e];
#pragma unroll
        for (int i = 0; i < 4; i++)
#pragma unroll
            for (int j = 0; j < 4; j++) acc[i][j] = fmaf(mv[i], wv[j], acc[i][j]);
    }

    float* lbase = g_logits + n * (2 * CC * CC);
#pragma unroll
    for (int i = 0; i < 4; i++) {
        int ci = 4 * r + i;
#pragma unroll
        for (int j = 0; j < 4; j++) {
            int dj = 4 * q + j;
            float L = acc[i][j] + sb[ci] * su[dj] + su[ci] * sb[dj]
                    + 16384.0f * sb[ci] * sb[dj];
            lbase[(mat * CC + ci) * CC + dj] = L;
        }
    }
}

// ---------------------------------------------------------------------------
// Kernel 3: softmax (unchanged)
// ---------------------------------------------------------------------------
__global__ void __launch_bounds__(256) softmax_kernel() {
    __shared__ float sE[128][64];
    __shared__ float sred[256];

    int n = blockIdx.x;
    int tid = threadIdx.x;
    int col = tid & 63, q = tid >> 6;
    const float* L = g_logits + n * 8192;

    float m = -3.0e38f;
    for (int k = 32 * q; k < 32 * q + 32; k++) {
        float v = L[k * 64 + col];
        sE[k][col] = v;
        m = fmaxf(m, v);
    }
    sred[tid] = m;
    __syncthreads();
    m = fmaxf(fmaxf(sred[col], sred[64 + col]),
              fmaxf(sred[128 + col], sred[192 + col]));
    __syncthreads();

    float s = 0.0f;
    for (int k = 32 * q; k < 32 * q + 32; k++) {
        float e = __expf(sE[k][col] - m);
        sE[k][col] = e;
        s += e;
    }
    sred[tid] = s;
    __syncthreads();
    s = (sred[col] + sred[64 + col]) + (sred[128 + col] + sred[192 + col]);
    float inv = 1.0f / s;

    float* A = g_att + n * 8192;
    for (int k = 32 * q; k < 32 * q + 32; k++)
        A[k * 64 + col] = sE[k][col] * inv;
}

// ---------------------------------------------------------------------------
// Kernel 4: out via bf16 mma.sync m16n8k16, 3-stream split. (R12/R14 version)
// 256 threads (8 warps), warp tile 64px x 32c, __launch_bounds__(256, 2).
// ---------------------------------------------------------------------------
#define OSM_ATT1 0
#define OSM_ATT2 18432
#define OSM_X1   36864
#define OSM_X2   53760
#define OSM_TOT  70656

__global__ void __launch_bounds__(256, 2) out_mma_kernel(const float* __restrict__ xR,
                                                         const float* __restrict__ xT,
                                                         float* __restrict__ out) {
    extern __shared__ __align__(16) char osm[];
    uint32_t sb = smem_u32(osm);

    int n  = blockIdx.y;
    int pb = blockIdx.x * 256;
    int tid = threadIdx.x;
    int w = tid >> 5;
    int lane = tid & 31;
    int wp = w & 3;      // px quarter (64 px)
    int wc = w >> 2;     // col half (32 c)

    // ---- stage att: [k 128][c 64] -> bf16 splits, stride 144B ----
    {
        const float2* attp = (const float2*)(g_att + n * 8192);
#pragma unroll
        for (int i = 0; i < 16; i++) {
            int f2 = tid + i * 256;
            int k = f2 >> 5, c2 = f2 & 31;
            float2 v = attp[f2];
            float h0 = bf16hi_f32(v.x), h1 = bf16hi_f32(v.y);
            uint32_t p1 = pack_bf16x2(h0, h1);
            uint32_t p2 = pack_bf16x2(v.x - h0, v.y - h1);
            uint32_t a = sb + k * 144 + c2 * 4;
            asm volatile("st.shared.b32 [%0], %1;" :: "r"(a + OSM_ATT1), "r"(p1) : "memory");
            asm volatile("st.shared.b32 [%0], %1;" :: "r"(a + OSM_ATT2), "r"(p2) : "memory");
        }
    }

    // lane addressing for trans ldmatrix
    int aK  = (lane & 7) + ((lane >> 4) << 3);   // A: k row
    int aP  = ((lane >> 3) & 1) << 3;            // A: +8 px
    int bK  = lane & 15;                         // B: k row
    int bC  = (lane >> 4) << 3;                  // B: +8 c

    int p0w = wp * 64;
    int c0w = wc * 32;

    float acc[4][4][4];   // [mt 16px][nt 8c][frag]
#pragma unroll
    for (int i = 0; i < 4; i++)
#pragma unroll
        for (int j = 0; j < 4; j++)
#pragma unroll
            for (int c = 0; c < 4; c++) acc[i][j][c] = 0.0f;

    const float* baseR = xR + n * CWH + pb;
    const float* baseT = xT + n * CWH + pb;

#pragma unroll 1
    for (int half = 0; half < 2; half++) {
        const float* xsrc = half ? baseT : baseR;
#pragma unroll 1
        for (int chunk = 0; chunk < 2; chunk++) {
            // ---- stage x chunk: [k 32][p 256] bf16 splits, stride 528B ----
            __syncthreads();
            const float* cs = xsrc + (chunk * 32) * WHT;
#pragma unroll
            for (int i = 0; i < 8; i++) {
                int fq = tid + i * 256;
                int kr = fq >> 6, pq = fq & 63;
                float4 v = *(const float4*)(cs + kr * WHT + pq * 4);
                float h0 = bf16hi_f32(v.x), h1 = bf16hi_f32(v.y);
                float h2 = bf16hi_f32(v.z), h3 = bf16hi_f32(v.w);
                uint32_t q10 = pack_bf16x2(h0, h1);
                uint32_t q11 = pack_bf16x2(h2, h3);
                uint32_t q20 = pack_bf16x2(v.x - h0, v.y - h1);
                uint32_t q21 = pack_bf16x2(v.z - h2, v.w - h3);
                uint32_t a = sb + kr * 528 + pq * 8;
                asm volatile("st.shared.v2.b32 [%0], {%1,%2};" ::
                             "r"(a + OSM_X1), "r"(q10), "r"(q11) : "memory");
                asm volatile("st.shared.v2.b32 [%0], {%1,%2};" ::
                             "r"(a + OSM_X2), "r"(q20), "r"(q21) : "memory");
            }
            __syncthreads();

#pragma unroll
            for (int k16 = 0; k16 < 2; k16++) {
                int kg = half * 64 + chunk * 32 + k16 * 16;   // global k for att
                uint32_t B1[2][4], B2[2][4];
#pragma unroll
                for (int nh = 0; nh < 2; nh++) {
                    uint32_t a = sb + (kg + bK) * 144 + (c0w + nh * 16 + bC) * 2;
                    ldsm4t(B1[nh], a + OSM_ATT1);
                    ldsm4t(B2[nh], a + OSM_ATT2);
                }
#pragma unroll
                for (int mt = 0; mt < 4; mt++) {
                    uint32_t A1[4], A2[4];
                    uint32_t a = sb + (k16 * 16 + aK) * 528
                               + (p0w + mt * 16 + aP) * 2;
                    ldsm4t(A1, a + OSM_X1);
                    ldsm4t(A2, a + OSM_X2);
#pragma unroll
                    for (int nh = 0; nh < 2; nh++)
#pragma unroll
                        for (int s = 0; s < 2; s++) {
                            const uint32_t* b1 = &B1[nh][s * 2];
                            const uint32_t* b2 = &B2[nh][s * 2];
                            float* d = acc[mt][nh * 2 + s];
                            mma16bf(d, A1, b1);   // x_hi * att_hi
                            mma16bf(d, A2, b1);   // x_lo * att_hi
                            mma16bf(d, A1, b2);   // x_hi * att_lo
                        }
                }
            }
        }
    }

    // ---- epilogue: D[p][c] -> out[c][p] ----
    float* ob = out + n * CWH + pb;
    int pr = lane >> 2;
    int cr = (lane & 3) * 2;
#pragma unroll
    for (int mt = 0; mt < 4; mt++) {
        int p = p0w + mt * 16 + pr;
#pragma unroll
        for (int nt = 0; nt < 4; nt++) {
            int c = c0w + nt * 8 + cr;
            float* d = acc[mt][nt];
            ob[c * WHT + p]           = d[0];
            ob[(c + 1) * WHT + p]     = d[1];
            ob[c * WHT + p + 8]       = d[2];
            ob[(c + 1) * WHT + p + 8] = d[3];
        }
    }
}

// ---------------------------------------------------------------------------
extern "C" void kernel_launch(void* const* d_in, const int* in_sizes, int n_in,
                              void* d_out, int out_size) {
    const float* xR = (const float*)d_in[0];
    const float* xT = (const float*)d_in[1];
    const float* WR = (const float*)d_in[2];
    const float* bR = (const float*)d_in[3];
    const float* WT = (const float*)d_in[4];
    const float* bT = (const float*)d_in[5];
    float* out = (float*)d_out;

    cudaFuncSetAttribute(out_mma_kernel,
                         cudaFuncAttributeMaxDynamicSharedMemorySize, OSM_TOT);

    gram_mma_kernel<<<2 * NB * SPLITS, 128>>>(xR, xT);
    logits_kernel<<<2 * NB, 256>>>(WR, bR, WT, bT);
    softmax_kernel<<<NB, 256>>>();
    out_mma_kernel<<<dim3(WHT / 256, NB), 256, OSM_TOT>>>(xR, xT, out);
}

// round 16
// speedup vs baseline: 1.1487x; 1.1487x over previous
#include <cuda_runtime.h>
#include <cuda_bf16.h>
#include <cstdint>

#define NB     16
#define CC     64
#define WHT    16384
#define CWH    (CC * WHT)
#define SPLITS 32

// Scratch (device globals; allocation is forbidden)
__device__ float g_gram_part[2 * NB * SPLITS * CC * CC];
__device__ float g_sums_part[2 * NB * SPLITS * CC];
__device__ float g_l2_part[2 * NB * SPLITS * CC];    // per-channel sum of lo^2
__device__ float g_logits[NB * 2 * CC * CC];
__device__ float g_att[NB * 2 * CC * CC];

__device__ __forceinline__ uint32_t smem_u32(const void* p) {
    uint32_t a;
    asm("{ .reg .u64 t; cvta.to.shared.u64 t, %1; cvt.u32.u64 %0, t; }" : "=r"(a) : "l"(p));
    return a;
}
__device__ __forceinline__ void ldsm4(uint32_t* r, uint32_t addr) {
    asm volatile("ldmatrix.sync.aligned.m8n8.x4.shared.b16 {%0,%1,%2,%3}, [%4];"
                 : "=r"(r[0]), "=r"(r[1]), "=r"(r[2]), "=r"(r[3]) : "r"(addr));
}
__device__ __forceinline__ void ldsm4t(uint32_t* r, uint32_t addr) {
    asm volatile("ldmatrix.sync.aligned.m8n8.x4.trans.shared.b16 {%0,%1,%2,%3}, [%4];"
                 : "=r"(r[0]), "=r"(r[1]), "=r"(r[2]), "=r"(r[3]) : "r"(addr));
}
__device__ __forceinline__ void mma16bf(float* d, const uint32_t* a, const uint32_t* b) {
    asm volatile(
        "mma.sync.aligned.m16n8k16.row.col.f32.bf16.bf16.f32 "
        "{%0,%1,%2,%3}, {%4,%5,%6,%7}, {%8,%9}, {%0,%1,%2,%3};"
        : "+f"(d[0]), "+f"(d[1]), "+f"(d[2]), "+f"(d[3])
        : "r"(a[0]), "r"(a[1]), "r"(a[2]), "r"(a[3]), "r"(b[0]), "r"(b[1]));
}
__device__ __forceinline__ uint32_t pack_bf16x2(float e0, float e1) {
    uint32_t r;
    asm("cvt.rn.bf16x2.f32 %0, %1, %2;" : "=r"(r) : "f"(e1), "f"(e0));
    return r;
}
__device__ __forceinline__ float bf16hi_f32(float x) {
    __nv_bfloat16 b = __float2bfloat16_rn(x);
    return __bfloat162float(b);
}

// ---------------------------------------------------------------------------
// Kernel 1: gram partials via bf16 mma.sync m16n8k16 hi/lo (3 streams),
// double-buffered, quadrant warp ownership.
// Y staged as bf16: [128 rows (0-63 hi, 64-127 lo)][32 px], row stride 80 B.
// Per warp (32x32 quadrant, all 2 k16 chunks) per iter: 16 ldsm + 48 mma
// (halved vs tf32 k8). Dropped ll^T diagonal corrected via g_l2_part.
// grid = 2*16*32 = 1024 blocks (mat, n, split of 512 px), 128 threads.
// ---------------------------------------------------------------------------
__global__ void __launch_bounds__(128, 5) gram_mma_kernel(const float* __restrict__ xR,
                                                          const float* __restrict__ xT) {
    __shared__ uint32_t sY[2][128 * 20];   // 2 x 10240 B ping-pong (80 B rows)

    int bid = blockIdx.x;
    int split = bid & 31;
    int n = (bid >> 5) & 15;
    int mat = bid >> 9;
    const float* src = (mat ? xT : xR) + n * CWH;

    int tid = threadIdx.x;
    int w = tid >> 5;
    int lane = tid & 31;
    int mrow = (w >> 1) * 32;   // quadrant row base
    int ncol = (w & 1) * 32;    // quadrant col base

    int sc = tid >> 1;          // staging channel
    int seg = tid & 1;          // 16-px segment
    const float* gsrc = src + sc * WHT + split * 512 + seg * 16;

    uint32_t buf0 = smem_u32(sY[0]);
    uint32_t stoff_hi = (uint32_t)(sc * 80 + seg * 32);
    uint32_t stoff_lo = stoff_hi + 64 * 80;

    // ldsm lane addressing (same formulas as validated tf32 path; bf16 data)
    int q  = lane >> 3;
    int r8 = lane & 7;
    int a_row  = r8 + ((q & 1) << 3);
    int a_colb = (q >> 1) << 4;
    int b_row  = r8 + ((q >> 1) << 3);
    int b_colb = (q & 1) << 4;

    float acc[2][4][4];
#pragma unroll
    for (int i = 0; i < 2; i++)
#pragma unroll
        for (int j = 0; j < 4; j++)
#pragma unroll
            for (int e = 0; e < 4; e++) acc[i][j][e] = 0.0f;
    float csum = 0.0f, csum2 = 0.0f;

    float4 v[4];
#pragma unroll
    for (int i = 0; i < 4; i++) v[i] = *(const float4*)(gsrc + 4 * i);
    // stage t=0 into buf 0
    {
        uint32_t hi = buf0 + stoff_hi, lo = buf0 + stoff_lo;
        uint32_t qh[4], ql[4];
#pragma unroll
        for (int i = 0; i < 4; i++) {
            float4 x = v[i];
            csum += (x.x + x.y) + (x.z + x.w);
            float h0 = bf16hi_f32(x.x), h1 = bf16hi_f32(x.y);
            float h2 = bf16hi_f32(x.z), h3 = bf16hi_f32(x.w);
            float l0 = x.x - h0, l1 = x.y - h1, l2 = x.z - h2, l3 = x.w - h3;
            csum2 += (l0 * l0 + l1 * l1) + (l2 * l2 + l3 * l3);
            qh[(i & 1) * 2]     = pack_bf16x2(h0, h1);
            qh[(i & 1) * 2 + 1] = pack_bf16x2(h2, h3);
            ql[(i & 1) * 2]     = pack_bf16x2(l0, l1);
            ql[(i & 1) * 2 + 1] = pack_bf16x2(l2, l3);
            if (i & 1) {
                uint32_t off = (i >> 1) * 16;
                asm volatile("st.shared.v4.b32 [%0], {%1,%2,%3,%4};" ::
                             "r"(hi + off), "r"(qh[0]), "r"(qh[1]), "r"(qh[2]), "r"(qh[3]) : "memory");
                asm volatile("st.shared.v4.b32 [%0], {%1,%2,%3,%4};" ::
                             "r"(lo + off), "r"(ql[0]), "r"(ql[1]), "r"(ql[2]), "r"(ql[3]) : "memory");
            }
        }
    }
    __syncthreads();

#pragma unroll 1
    for (int t = 0; t < 16; t++) {
        uint32_t cbuf = buf0 + (uint32_t)((t & 1) * 10240);
        uint32_t nbuf = buf0 + (uint32_t)(((t + 1) & 1) * 10240);

        // (1) issue global loads for t+1 (non-blocking)
        if (t < 15) {
            const float* nxt = gsrc + (t + 1) * 32;
#pragma unroll
            for (int i = 0; i < 4; i++) v[i] = *(const float4*)(nxt + 4 * i);
        }

        // (2) compute: 2 k16 chunks on this warp's quadrant
#pragma unroll
        for (int k16 = 0; k16 < 2; k16++) {
            uint32_t kb = (uint32_t)(k16 * 32);
            uint32_t Ah[2][4], Al[2][4], Bh[2][4], Bl[2][4];
#pragma unroll
            for (int mt = 0; mt < 2; mt++) {
                uint32_t addr = cbuf + (mrow + mt * 16 + a_row) * 80 + kb + a_colb;
                ldsm4(Ah[mt], addr);
                ldsm4(Al[mt], addr + 64 * 80);
            }
#pragma unroll
            for (int nt16 = 0; nt16 < 2; nt16++) {
                uint32_t addr = cbuf + (ncol + nt16 * 16 + b_row) * 80 + kb + b_colb;
                ldsm4(Bh[nt16], addr);
                ldsm4(Bl[nt16], addr + 64 * 80);
            }
#pragma unroll
            for (int mt = 0; mt < 2; mt++)
#pragma unroll
                for (int nt = 0; nt < 4; nt++) {
                    const uint32_t* bh = &Bh[nt >> 1][(nt & 1) * 2];
                    const uint32_t* bl = &Bl[nt >> 1][(nt & 1) * 2];
                    mma16bf(acc[mt][nt], Ah[mt], bh);   // hi*hi
                    mma16bf(acc[mt][nt], Ah[mt], bl);   // hi*lo
                    mma16bf(acc[mt][nt], Al[mt], bh);   // lo*hi
                }
        }

        // (3) cvt + store t+1 into nbuf (stalls on LDG here, after mma issued)
        if (t < 15) {
            uint32_t hi = nbuf + stoff_hi, lo = nbuf + stoff_lo;
            uint32_t qh[4], ql[4];
#pragma unroll
            for (int i = 0; i < 4; i++) {
                float4 x = v[i];
                csum += (x.x + x.y) + (x.z + x.w);
                float h0 = bf16hi_f32(x.x), h1 = bf16hi_f32(x.y);
                float h2 = bf16hi_f32(x.z), h3 = bf16hi_f32(x.w);
                float l0 = x.x - h0, l1 = x.y - h1, l2 = x.z - h2, l3 = x.w - h3;
                csum2 += (l0 * l0 + l1 * l1) + (l2 * l2 + l3 * l3);
                qh[(i & 1) * 2]     = pack_bf16x2(h0, h1);
                qh[(i & 1) * 2 + 1] = pack_bf16x2(h2, h3);
                ql[(i & 1) * 2]     = pack_bf16x2(l0, l1);
                ql[(i & 1) * 2 + 1] = pack_bf16x2(l2, l3);
                if (i & 1) {
                    uint32_t off = (i >> 1) * 16;
                    asm volatile("st.shared.v4.b32 [%0], {%1,%2,%3,%4};" ::
                                 "r"(hi + off), "r"(qh[0]), "r"(qh[1]), "r"(qh[2]), "r"(qh[3]) : "memory");
                    asm volatile("st.shared.v4.b32 [%0], {%1,%2,%3,%4};" ::
                                 "r"(lo + off), "r"(ql[0]), "r"(ql[1]), "r"(ql[2]), "r"(ql[3]) : "memory");
                }
            }
        }
        __syncthreads();
    }

    // channel sums + lo^2 sums (tid pairs share a channel)
    csum  += __shfl_xor_sync(0xffffffffu, csum, 1);
    csum2 += __shfl_xor_sync(0xffffffffu, csum2, 1);
    if (seg == 0) {
        g_sums_part[((mat * NB + n) * SPLITS + split) * 64 + sc] = csum;
        g_l2_part[((mat * NB + n) * SPLITS + split) * 64 + sc]  = csum2;
    }

    // direct write: each warp owns a disjoint 32x32 quadrant
    {
        float* gb = g_gram_part + ((mat * NB + n) * SPLITS + split) * 4096;
        int gr = lane >> 2, tig = lane & 3;
#pragma unroll
        for (int mt = 0; mt < 2; mt++)
#pragma unroll
            for (int nt = 0; nt < 4; nt++) {
                int row = mrow + mt * 16 + gr;
                int col = ncol + nt * 8 + 2 * tig;
                *(float2*)&gb[row * 64 + col] =
                    make_float2(acc[mt][nt][0], acc[mt][nt][1]);
                *(float2*)&gb[(row + 8) * 64 + col] =
                    make_float2(acc[mt][nt][2], acc[mt][nt][3]);
            }
    }
}

// ---------------------------------------------------------------------------
// Kernel 2: logits  S = W G W^T + b u^T + u b^T + WH b b^T  (per n, per mat)
// G diagonal corrected by + sum(lo^2) (the dropped ll^T diagonal bias).
// ---------------------------------------------------------------------------
__global__ void __launch_bounds__(256) logits_kernel(const float* __restrict__ WR,
                                                     const float* __restrict__ bR,
                                                     const float* __restrict__ WT,
                                                     const float* __restrict__ bT) {
    int n = blockIdx.x & 15;
    int mat = blockIdx.x >> 4;
    const float* W  = mat ? WT : WR;
    const float* bv = mat ? bT : bR;

    __shared__ float sW[64][64];
    __shared__ float sGM[64][65];
    __shared__ float sb[64], ssum[64], su[64];

    int tid = threadIdx.x;
    for (int i = tid; i < 1024; i += 256)
        ((float4*)&sW[0][0])[i] = ((const float4*)W)[i];

    const float4* gp = (const float4*)(g_gram_part + (mat * NB + n) * SPLITS * 4096);
    for (int i = tid; i < 1024; i += 256) {
        float4 a = gp[i];
#pragma unroll
        for (int s = 1; s < SPLITS; s++) {
            float4 b = gp[s * 1024 + i];
            a.x += b.x; a.y += b.y; a.z += b.z; a.w += b.w;
        }
        int row = i >> 4, col = (i & 15) * 4;
        sGM[row][col] = a.x; sGM[row][col + 1] = a.y;
        sGM[row][col + 2] = a.z; sGM[row][col + 3] = a.w;
    }
    if (tid < 64) {
        sb[tid] = bv[tid];
        const float* sp = g_sums_part + (mat * NB + n) * SPLITS * 64 + tid;
        float s = 0.0f;
#pragma unroll
        for (int k = 0; k < SPLITS; k++) s += sp[k * 64];
        ssum[tid] = s;
    }
    __syncthreads();

    if (tid < 64) {
        // diagonal correction: add sum of lo^2 (dropped ll^T diagonal)
        const float* lp = g_l2_part + (mat * NB + n) * SPLITS * 64 + tid;
        float s2 = 0.0f;
#pragma unroll
        for (int k = 0; k < SPLITS; k++) s2 += lp[k * 64];
        sGM[tid][tid] += s2;

        float u = 0.0f;
        for (int f = 0; f < 64; f++) u += sW[tid][f] * ssum[f];
        su[tid] = u;
    }
    __syncthreads();

    int r = tid >> 4, q = tid & 15;
    float acc[4][4];
#pragma unroll
    for (int i = 0; i < 4; i++)
#pragma unroll
        for (int j = 0; j < 4; j++) acc[i][j] = 0.0f;
    for (int f = 0; f < 64; f++) {
        float wv[4], gv[4];
#pragma unroll
        for (int i = 0; i < 4; i++) wv[i] = sW[4 * r + i][f];
#pragma unroll
        for (int j = 0; j < 4; j++) gv[j] = sGM[f][4 * q + j];
#pragma unroll
        for (int i = 0; i < 4; i++)
#pragma unroll
            for (int j = 0; j < 4; j++) acc[i][j] = fmaf(wv[i], gv[j], acc[i][j]);
    }
    __syncthreads();
#pragma unroll
    for (int i = 0; i < 4; i++)
#pragma unroll
        for (int j = 0; j < 4; j++) sGM[4 * r + i][4 * q + j] = acc[i][j];
    __syncthreads();

#pragma unroll
    for (int i = 0; i < 4; i++)
#pragma unroll
        for (int j = 0; j < 4; j++) acc[i][j] = 0.0f;
    for (int e = 0; e < 64; e++) {
        float mv[4], wv[4];
#pragma unroll
        for (int i = 0; i < 4; i++) mv[i] = sGM[4 * r + i][e];
#pragma unroll
        for (int j = 0; j < 4; j++) wv[j] = sW[4 * q + j][e];
#pragma unroll
        for (int i = 0; i < 4; i++)
#pragma unroll
            for (int j = 0; j < 4; j++) acc[i][j] = fmaf(mv[i], wv[j], acc[i][j]);
    }

    float* lbase = g_logits + n * (2 * CC * CC);
#pragma unroll
    for (int i = 0; i < 4; i++) {
        int ci = 4 * r + i;
#pragma unroll
        for (int j = 0; j < 4; j++) {
            int dj = 4 * q + j;
            float L = acc[i][j] + sb[ci] * su[dj] + su[ci] * sb[dj]
                    + 16384.0f * sb[ci] * sb[dj];
            lbase[(mat * CC + ci) * CC + dj] = L;
        }
    }
}

// ---------------------------------------------------------------------------
// Kernel 3: softmax (unchanged)
// ---------------------------------------------------------------------------
__global__ void __launch_bounds__(256) softmax_kernel() {
    __shared__ float sE[128][64];
    __shared__ float sred[256];

    int n = blockIdx.x;
    int tid = threadIdx.x;
    int col = tid & 63, q = tid >> 6;
    const float* L = g_logits + n * 8192;

    float m = -3.0e38f;
    for (int k = 32 * q; k < 32 * q + 32; k++) {
        float v = L[k * 64 + col];
        sE[k][col] = v;
        m = fmaxf(m, v);
    }
    sred[tid] = m;
    __syncthreads();
    m = fmaxf(fmaxf(sred[col], sred[64 + col]),
              fmaxf(sred[128 + col], sred[192 + col]));
    __syncthreads();

    float s = 0.0f;
    for (int k = 32 * q; k < 32 * q + 32; k++) {
        float e = __expf(sE[k][col] - m);
        sE[k][col] = e;
        s += e;
    }
    sred[tid] = s;
    __syncthreads();
    s = (sred[col] + sred[64 + col]) + (sred[128 + col] + sred[192 + col]);
    float inv = 1.0f / s;

    float* A = g_att + n * 8192;
    for (int k = 32 * q; k < 32 * q + 32; k++)
        A[k * 64 + col] = sE[k][col] * inv;
}

// ---------------------------------------------------------------------------
// Kernel 4: out via bf16 mma.sync m16n8k16, 3-stream split. (R12/R14 version)
// 256 threads (8 warps), warp tile 64px x 32c, __launch_bounds__(256, 2).
// ---------------------------------------------------------------------------
#define OSM_ATT1 0
#define OSM_ATT2 18432
#define OSM_X1   36864
#define OSM_X2   53760
#define OSM_TOT  70656

__global__ void __launch_bounds__(256, 2) out_mma_kernel(const float* __restrict__ xR,
                                                         const float* __restrict__ xT,
                                                         float* __restrict__ out) {
    extern __shared__ __align__(16) char osm[];
    uint32_t sb = smem_u32(osm);

    int n  = blockIdx.y;
    int pb = blockIdx.x * 256;
    int tid = threadIdx.x;
    int w = tid >> 5;
    int lane = tid & 31;
    int wp = w & 3;      // px quarter (64 px)
    int wc = w >> 2;     // col half (32 c)

    // ---- stage att: [k 128][c 64] -> bf16 splits, stride 144B ----
    {
        const float2* attp = (const float2*)(g_att + n * 8192);
#pragma unroll
        for (int i = 0; i < 16; i++) {
            int f2 = tid + i * 256;
            int k = f2 >> 5, c2 = f2 & 31;
            float2 v = attp[f2];
            float h0 = bf16hi_f32(v.x), h1 = bf16hi_f32(v.y);
            uint32_t p1 = pack_bf16x2(h0, h1);
            uint32_t p2 = pack_bf16x2(v.x - h0, v.y - h1);
            uint32_t a = sb + k * 144 + c2 * 4;
            asm volatile("st.shared.b32 [%0], %1;" :: "r"(a + OSM_ATT1), "r"(p1) : "memory");
            asm volatile("st.shared.b32 [%0], %1;" :: "r"(a + OSM_ATT2), "r"(p2) : "memory");
        }
    }

    // lane addressing for trans ldmatrix
    int aK  = (lane & 7) + ((lane >> 4) << 3);   // A: k row
    int aP  = ((lane >> 3) & 1) << 3;            // A: +8 px
    int bK  = lane & 15;                         // B: k row
    int bC  = (lane >> 4) << 3;                  // B: +8 c

    int p0w = wp * 64;
    int c0w = wc * 32;

    float acc[4][4][4];   // [mt 16px][nt 8c][frag]
#pragma unroll
    for (int i = 0; i < 4; i++)
#pragma unroll
        for (int j = 0; j < 4; j++)
#pragma unroll
            for (int c = 0; c < 4; c++) acc[i][j][c] = 0.0f;

    const float* baseR = xR + n * CWH + pb;
    const float* baseT = xT + n * CWH + pb;

#pragma unroll 1
    for (int half = 0; half < 2; half++) {
        const float* xsrc = half ? baseT : baseR;
#pragma unroll 1
        for (int chunk = 0; chunk < 2; chunk++) {
            // ---- stage x chunk: [k 32][p 256] bf16 splits, stride 528B ----
            __syncthreads();
            const float* cs = xsrc + (chunk * 32) * WHT;
#pragma unroll
            for (int i = 0; i < 8; i++) {
                int fq = tid + i * 256;
                int kr = fq >> 6, pq = fq & 63;
                float4 v = *(const float4*)(cs + kr * WHT + pq * 4);
                float h0 = bf16hi_f32(v.x), h1 = bf16hi_f32(v.y);
                float h2 = bf16hi_f32(v.z), h3 = bf16hi_f32(v.w);
                uint32_t q10 = pack_bf16x2(h0, h1);
                uint32_t q11 = pack_bf16x2(h2, h3);
                uint32_t q20 = pack_bf16x2(v.x - h0, v.y - h1);
                uint32_t q21 = pack_bf16x2(v.z - h2, v.w - h3);
                uint32_t a = sb + kr * 528 + pq * 8;
                asm volatile("st.shared.v2.b32 [%0], {%1,%2};" ::
                             "r"(a + OSM_X1), "r"(q10), "r"(q11) : "memory");
                asm volatile("st.shared.v2.b32 [%0], {%1,%2};" ::
                             "r"(a + OSM_X2), "r"(q20), "r"(q21) : "memory");
            }
            __syncthreads();

#pragma unroll
            for (int k16 = 0; k16 < 2; k16++) {
                int kg = half * 64 + chunk * 32 + k16 * 16;   // global k for att
                uint32_t B1[2][4], B2[2][4];
#pragma unroll
                for (int nh = 0; nh < 2; nh++) {
                    uint32_t a = sb + (kg + bK) * 144 + (c0w + nh * 16 + bC) * 2;
                    ldsm4t(B1[nh], a + OSM_ATT1);
                    ldsm4t(B2[nh], a + OSM_ATT2);
                }
#pragma unroll
                for (int mt = 0; mt < 4; mt++) {
                    uint32_t A1[4], A2[4];
                    uint32_t a = sb + (k16 * 16 + aK) * 528
                               + (p0w + mt * 16 + aP) * 2;
                    ldsm4t(A1, a + OSM_X1);
                    ldsm4t(A2, a + OSM_X2);
#pragma unroll
                    for (int nh = 0; nh < 2; nh++)
#pragma unroll
                        for (int s = 0; s < 2; s++) {
                            const uint32_t* b1 = &B1[nh][s * 2];
                            const uint32_t* b2 = &B2[nh][s * 2];
                            float* d = acc[mt][nh * 2 + s];
                            mma16bf(d, A1, b1);   // x_hi * att_hi
                            mma16bf(d, A2, b1);   // x_lo * att_hi
                            mma16bf(d, A1, b2);   // x_hi * att_lo
                        }
                }
            }
        }
    }

    // ---- epilogue: D[p][c] -> out[c][p] ----
    float* ob = out + n * CWH + pb;
    int pr = lane >> 2;
    int cr = (lane & 3) * 2;
#pragma unroll
    for (int mt = 0; mt < 4; mt++) {
        int p = p0w + mt * 16 + pr;
#pragma unroll
        for (int nt = 0; nt < 4; nt++) {
            int c = c0w + nt * 8 + cr;
            float* d = acc[mt][nt];
            ob[c * WHT + p]           = d[0];
            ob[(c + 1) * WHT + p]     = d[1];
            ob[c * WHT + p + 8]       = d[2];
            ob[(c + 1) * WHT + p + 8] = d[3];
        }
    }
}

// ---------------------------------------------------------------------------
extern "C" void kernel_launch(void* const* d_in, const int* in_sizes, int n_in,
                              void* d_out, int out_size) {
    const float* xR = (const float*)d_in[0];
    const float* xT = (const float*)d_in[1];
    const float* WR = (const float*)d_in[2];
    const float* bR = (const float*)d_in[3];
    const float* WT = (const float*)d_in[4];
    const float* bT = (const float*)d_in[5];
    float* out = (float*)d_out;

    cudaFuncSetAttribute(out_mma_kernel,
                         cudaFuncAttributeMaxDynamicSharedMemorySize, OSM_TOT);

    gram_mma_kernel<<<2 * NB * SPLITS, 128>>>(xR, xT);
    logits_kernel<<<2 * NB, 256>>>(WR, bR, WT, bT);
    softmax_kernel<<<NB, 256>>>();
    out_mma_kernel<<<dim3(WHT / 256, NB), 256, OSM_TOT>>>(xR, xT, out);
}